// round 12
// baseline (speedup 1.0000x reference)
#include <cuda_runtime.h>
#include <cuda_bf16.h>
#include <math.h>
#include <stdint.h>

#define T_STEPS 512
#define BATCH   64
#define IN_DIM  1024
#define HID     1024
#define GATES   4096   // 4*HID, gate order i,g,f,o
#define NCTA    128

// ---------------- device scratch ----------------
__device__ float g_wx[(size_t)T_STEPS * BATCH * GATES];   // 512 MB
__device__ unsigned g_arrive[NCTA * 8];                   // 32B-strided per-CTA step flags
__device__ unsigned g_bar;                                // end-of-launch cleanup

__device__ __nv_bfloat16 g_xhi[(size_t)T_STEPS * BATCH * IN_DIM];
__device__ __nv_bfloat16 g_xlo[(size_t)T_STEPS * BATCH * IN_DIM];
__device__ __nv_bfloat16 g_Wthi[(size_t)GATES * IN_DIM];   // transposed [N][K]
__device__ __nv_bfloat16 g_Wtlo[(size_t)GATES * IN_DIM];
__device__ __nv_bfloat16 g_Rthi[(size_t)GATES * HID];      // transposed [N][K]
__device__ __nv_bfloat16 g_Rtlo[(size_t)GATES * HID];
__device__ __nv_bfloat16 g_hhi[2][BATCH * HID];            // ping-pong h bf16 hi/lo
__device__ __nv_bfloat16 g_hlo[2][BATCH * HID];

// ---------------- helpers ----------------
__device__ __forceinline__ void mma16816(float* c, const uint32_t* a, const uint32_t* b)
{
    asm volatile(
        "mma.sync.aligned.m16n8k16.row.col.f32.bf16.bf16.f32 "
        "{%0,%1,%2,%3}, {%4,%5,%6,%7}, {%8,%9}, {%0,%1,%2,%3};"
        : "+f"(c[0]), "+f"(c[1]), "+f"(c[2]), "+f"(c[3])
        : "r"(a[0]), "r"(a[1]), "r"(a[2]), "r"(a[3]), "r"(b[0]), "r"(b[1]));
}

__device__ __forceinline__ void split_bf16(float v, __nv_bfloat16& hi, __nv_bfloat16& lo)
{
    hi = __float2bfloat16_rn(v);
    lo = __float2bfloat16_rn(v - __bfloat162float(hi));
}

__device__ __forceinline__ float tanh_fast(float x)
{
    float y;
    asm("tanh.approx.f32 %0, %1;" : "=f"(y) : "f"(x));
    return y;
}
__device__ __forceinline__ float sigmoid_fast(float x)
{
    return 0.5f * tanh_fast(0.5f * x) + 0.5f;
}

__device__ __forceinline__ float2 ldcg_f2(const float* p)
{
    float2 v;
    asm volatile("ld.global.cg.v2.f32 {%0,%1}, [%2];" : "=f"(v.x), "=f"(v.y) : "l"(p));
    return v;
}
__device__ __forceinline__ unsigned ldcg_u32(const void* p)
{
    unsigned v;
    asm volatile("ld.global.cg.u32 %0, [%1];" : "=r"(v) : "l"(p));
    return v;
}

// ---------------- conversion kernels ----------------
__global__ void convert_x(const float* __restrict__ x)
{
    size_t i = (size_t)blockIdx.x * blockDim.x + threadIdx.x;
    if (i < (size_t)T_STEPS * BATCH * IN_DIM) {
        __nv_bfloat16 hi, lo;
        split_bf16(x[i], hi, lo);
        g_xhi[i] = hi;
        g_xlo[i] = lo;
    }
}

__global__ void convert_W(const float* __restrict__ src)
{
    __shared__ float tile[32][33];
    int n0 = blockIdx.x * 32, k0 = blockIdx.y * 32;
    int tx = threadIdx.x, ty = threadIdx.y;
#pragma unroll
    for (int i = 0; i < 32; i += 8)
        tile[ty + i][tx] = src[(size_t)(k0 + ty + i) * GATES + n0 + tx];
    __syncthreads();
#pragma unroll
    for (int i = 0; i < 32; i += 8) {
        float v = tile[tx][ty + i];
        size_t o = (size_t)(n0 + ty + i) * IN_DIM + k0 + tx;
        __nv_bfloat16 hi, lo;
        split_bf16(v, hi, lo);
        g_Wthi[o] = hi;
        g_Wtlo[o] = lo;
    }
}

__global__ void convert_R(const float* __restrict__ src)
{
    __shared__ float tile[32][33];
    int n0 = blockIdx.x * 32, k0 = blockIdx.y * 32;
    int tx = threadIdx.x, ty = threadIdx.y;
#pragma unroll
    for (int i = 0; i < 32; i += 8)
        tile[ty + i][tx] = src[(size_t)(k0 + ty + i) * GATES + n0 + tx];
    __syncthreads();
#pragma unroll
    for (int i = 0; i < 32; i += 8) {
        float v = tile[tx][ty + i];
        size_t o = (size_t)(n0 + ty + i) * HID + k0 + tx;
        __nv_bfloat16 hi, lo;
        split_bf16(v, hi, lo);
        g_Rthi[o] = hi;
        g_Rtlo[o] = lo;
    }
}

// ---------------- wx GEMM: cp.async double-buffered (R11, proven) ----------------
#define WXS 40
#define WXC (128 * WXS)
#define WX_SMEM (2 * 4 * WXC * 2)       // 81920 B

__device__ __forceinline__ void wx_stage(uint32_t smb, size_t m0, int n0,
                                         int k0, int b, int tid)
{
    const __nv_bfloat16* srcs[4];
    srcs[0] = g_xhi;  srcs[1] = g_xlo;  srcs[2] = g_Wthi;  srcs[3] = g_Wtlo;
#pragma unroll
    for (int arr = 0; arr < 4; arr++) {
        size_t base = (arr < 2) ? m0 : (size_t)n0;
#pragma unroll
        for (int rep = 0; rep < 2; rep++) {
            int id = tid + rep * 256;
            int row = id >> 2, seg = id & 3;
            const __nv_bfloat16* src = srcs[arr]
                + (base + row) * IN_DIM + k0 + seg * 8;
            uint32_t dst = smb + (uint32_t)(((b * 4 + arr) * WXC
                                             + row * WXS + seg * 8) * 2);
            asm volatile("cp.async.cg.shared.global [%0], [%1], 16;"
                         :: "r"(dst), "l"(src));
        }
    }
    asm volatile("cp.async.commit_group;");
}

__global__ __launch_bounds__(256) void wx_mma(const float* __restrict__ bias)
{
    extern __shared__ __align__(16) unsigned char wxsm[];
    __nv_bfloat16* S = (__nv_bfloat16*)wxsm;
    uint32_t smb = (uint32_t)__cvta_generic_to_shared(S);

    int tid  = threadIdx.x;
    int lane = tid & 31, w = tid >> 5;
    int g = lane >> 2, tq = lane & 3;
    size_t m0 = (size_t)blockIdx.y * 128;
    int n0 = blockIdx.x * 128;
    int wm = w & 1, wn = w >> 1;

    float acc[4][4][4];
#pragma unroll
    for (int mt = 0; mt < 4; mt++)
#pragma unroll
        for (int nt = 0; nt < 4; nt++)
#pragma unroll
            for (int r = 0; r < 4; r++) acc[mt][nt][r] = 0.f;

    wx_stage(smb, m0, n0, 0, 0, tid);

    for (int kc = 0; kc < 32; kc++) {
        int cur = kc & 1;
        if (kc < 31) {
            wx_stage(smb, m0, n0, (kc + 1) * 32, cur ^ 1, tid);
            asm volatile("cp.async.wait_group 1;");
        } else {
            asm volatile("cp.async.wait_group 0;");
        }
        __syncthreads();

        const __nv_bfloat16* Ah = S + (cur * 4 + 0) * WXC;
        const __nv_bfloat16* Al = S + (cur * 4 + 1) * WXC;
        const __nv_bfloat16* Bh = S + (cur * 4 + 2) * WXC;
        const __nv_bfloat16* Bl = S + (cur * 4 + 3) * WXC;

#pragma unroll
        for (int ks = 0; ks < 2; ks++) {
            int ko = ks * 16;
            uint32_t bh[4][2], bl[4][2];
#pragma unroll
            for (int nt = 0; nt < 4; nt++) {
                int r = wn * 32 + nt * 8 + g;
                bh[nt][0] = *(const uint32_t*)&Bh[r * WXS + ko + 2 * tq];
                bh[nt][1] = *(const uint32_t*)&Bh[r * WXS + ko + 2 * tq + 8];
                bl[nt][0] = *(const uint32_t*)&Bl[r * WXS + ko + 2 * tq];
                bl[nt][1] = *(const uint32_t*)&Bl[r * WXS + ko + 2 * tq + 8];
            }
#pragma unroll
            for (int mt = 0; mt < 4; mt++) {
                int r0 = wm * 64 + mt * 16 + g, r1 = r0 + 8;
                uint32_t ah[4], al[4];
                ah[0] = *(const uint32_t*)&Ah[r0 * WXS + ko + 2 * tq];
                ah[1] = *(const uint32_t*)&Ah[r1 * WXS + ko + 2 * tq];
                ah[2] = *(const uint32_t*)&Ah[r0 * WXS + ko + 2 * tq + 8];
                ah[3] = *(const uint32_t*)&Ah[r1 * WXS + ko + 2 * tq + 8];
                al[0] = *(const uint32_t*)&Al[r0 * WXS + ko + 2 * tq];
                al[1] = *(const uint32_t*)&Al[r1 * WXS + ko + 2 * tq];
                al[2] = *(const uint32_t*)&Al[r0 * WXS + ko + 2 * tq + 8];
                al[3] = *(const uint32_t*)&Al[r1 * WXS + ko + 2 * tq + 8];
#pragma unroll
                for (int nt = 0; nt < 4; nt++) mma16816(acc[mt][nt], ah, bh[nt]);
#pragma unroll
                for (int nt = 0; nt < 4; nt++) mma16816(acc[mt][nt], ah, bl[nt]);
#pragma unroll
                for (int nt = 0; nt < 4; nt++) mma16816(acc[mt][nt], al, bh[nt]);
            }
        }
        __syncthreads();
    }

#pragma unroll
    for (int mt = 0; mt < 4; mt++) {
        size_t row = m0 + wm * 64 + mt * 16 + g;
#pragma unroll
        for (int nt = 0; nt < 4; nt++) {
            int col = n0 + wn * 32 + nt * 8 + 2 * tq;
            g_wx[row * GATES + col]           = acc[mt][nt][0] + bias[col];
            g_wx[row * GATES + col + 1]       = acc[mt][nt][1] + bias[col + 1];
            g_wx[(row + 8) * GATES + col]     = acc[mt][nt][2] + bias[col];
            g_wx[(row + 8) * GATES + col + 1] = acc[mt][nt][3] + bias[col + 1];
        }
    }
}

// ---------------- persistent LSTM recurrence v6 ----------------
// R9 skeleton (global flag-array barrier, proven) but h fragments are loaded
// DIRECTLY from L2 into mma registers (ld.global.cg.b32): kills the
// cp.async+smem staging pipeline whose LDGSTS issue cost (~2048 ops/warp/step
// x 8cyc) dominated the step. Chunk-level register double-buffering hides L2
// latency. Fragment sectors are fully utilized (a0+a2 of a row = one 32B line).
#define RSTR 1032
#define RED_OFF (2 * 32 * RSTR * 2)               // 132096 B
#define SMEM_PERS (RED_OFF + 2 * 128 * 9 * 4)     // +9216 B reduction

// Load one 64-k chunk of A-fragments (4 k16-tiles, hi+lo) into registers.
// base = &h[(wm*16+g)*HID + grp*512 + 2*tq]; per tile: a0,a1(row+8),a2(+8col),a3.
__device__ __forceinline__ void load_hfrag(uint32_t* fh, uint32_t* fl,
                                           const __nv_bfloat16* bhi,
                                           const __nv_bfloat16* blo, int kc)
{
#pragma unroll
    for (int kt = 0; kt < 4; kt++) {
        int o = kc * 64 + kt * 16;
        fh[kt * 4 + 0] = ldcg_u32(bhi + o);
        fh[kt * 4 + 1] = ldcg_u32(bhi + o + 8 * HID);
        fh[kt * 4 + 2] = ldcg_u32(bhi + o + 8);
        fh[kt * 4 + 3] = ldcg_u32(bhi + o + 8 * HID + 8);
        fl[kt * 4 + 0] = ldcg_u32(blo + o);
        fl[kt * 4 + 1] = ldcg_u32(blo + o + 8 * HID);
        fl[kt * 4 + 2] = ldcg_u32(blo + o + 8);
        fl[kt * 4 + 3] = ldcg_u32(blo + o + 8 * HID + 8);
    }
}

__global__ __launch_bounds__(256) void lstm_persistent(float* __restrict__ out_base)
{
    extern __shared__ __align__(16) unsigned char smem_raw[];
    __nv_bfloat16* Rh = (__nv_bfloat16*)smem_raw;
    __nv_bfloat16* Rl = Rh + 32 * RSTR;
    float* Red = (float*)(smem_raw + RED_OFF);

    const int tid  = threadIdx.x;
    const int lane = tid & 31, w = tid >> 5;
    const int g = lane >> 2, tq = lane & 3;
    const int grp = w >> 2, wm = w & 3;
    const int hc0 = blockIdx.x * 8;

    // load R slice into smem once
    for (int rep = 0; rep < 16; rep++) {
        int id = rep * 256 + tid;
        int row = id >> 7, seg = id & 127;
        size_t src = (size_t)((row >> 3) * HID + hc0 + (row & 7)) * HID + seg * 8;
        *(uint4*)&Rh[row * RSTR + seg * 8] = *(const uint4*)&g_Rthi[src];
        *(uint4*)&Rl[row * RSTR + seg * 8] = *(const uint4*)&g_Rtlo[src];
    }
    __syncthreads();

    const int fbase = (wm * 16 + g) * HID + grp * 512 + 2 * tq;  // fragment base offset
    float c_reg[2] = {0.f, 0.f};

    for (int t = 0; t < T_STEPS; t++) {
        // prefetch this group's wx half (DRAM, independent of h)
        float2 wxp[4];
        {
            const float* wx_t = g_wx + (size_t)t * BATCH * GATES;
            int brow = wm * 16 + g + grp * 8;
#pragma unroll
            for (int gate = 0; gate < 4; gate++)
                wxp[gate] = ldcg_f2(wx_t + (size_t)brow * GATES + gate * HID + hc0 + 2 * tq);
        }

        float acc[4][4];
#pragma unroll
        for (int nt = 0; nt < 4; nt++)
#pragma unroll
            for (int r = 0; r < 4; r++) acc[nt][r] = 0.f;

        if (t > 0) {
            const __nv_bfloat16* bhi = g_hhi[(t - 1) & 1] + fbase;
            const __nv_bfloat16* blo = g_hlo[(t - 1) & 1] + fbase;

            uint32_t fh[2][16], fl[2][16];
            load_hfrag(fh[0], fl[0], bhi, blo, 0);

            for (int kc = 0; kc < 8; kc++) {
                int cur = kc & 1;
                if (kc < 7)
                    load_hfrag(fh[cur ^ 1], fl[cur ^ 1], bhi, blo, kc + 1);

#pragma unroll
                for (int kt = 0; kt < 4; kt++) {
                    const uint32_t* ah = &fh[cur][kt * 4];
                    const uint32_t* al = &fl[cur][kt * 4];
                    int kR = grp * 512 + kc * 64 + kt * 16 + 2 * tq;
                    uint32_t bh[4][2], bl[4][2];
#pragma unroll
                    for (int nt = 0; nt < 4; nt++) {
                        int rr = nt * 8 + g;
                        bh[nt][0] = *(const uint32_t*)&Rh[rr * RSTR + kR];
                        bh[nt][1] = *(const uint32_t*)&Rh[rr * RSTR + kR + 8];
                        bl[nt][0] = *(const uint32_t*)&Rl[rr * RSTR + kR];
                        bl[nt][1] = *(const uint32_t*)&Rl[rr * RSTR + kR + 8];
                    }
#pragma unroll
                    for (int nt = 0; nt < 4; nt++) mma16816(acc[nt], ah, bh[nt]);
#pragma unroll
                    for (int nt = 0; nt < 4; nt++) mma16816(acc[nt], ah, bl[nt]);
#pragma unroll
                    for (int nt = 0; nt < 4; nt++) mma16816(acc[nt], al, bh[nt]);
                }
            }
        }

        // cross-group exchange: ship the jj-half this group does NOT own
        {
            float* slot = Red + ((grp ^ 1) * 128 + wm * 32 + lane) * 9;
            int jbase = (grp == 1) ? 0 : 2;
#pragma unroll
            for (int nt = 0; nt < 4; nt++) {
                slot[nt * 2 + 0] = acc[nt][jbase + 0];
                slot[nt * 2 + 1] = acc[nt][jbase + 1];
            }
        }
        __syncthreads();

        {
            const float* slot = Red + (grp * 128 + wm * 32 + lane) * 9;
            int jbase = grp * 2;
            float* h_out = out_base + (size_t)t * BATCH * HID;
            int cb = t & 1;
#pragma unroll
            for (int cm = 0; cm < 2; cm++) {
                int j = jbase + cm;
                int brow = wm * 16 + g + grp * 8;
                int col  = hc0 + 2 * tq + cm;
                float vi = acc[0][j] + slot[0 * 2 + cm] + (cm ? wxp[0].y : wxp[0].x);
                float vg = acc[1][j] + slot[1 * 2 + cm] + (cm ? wxp[1].y : wxp[1].x);
                float vf = acc[2][j] + slot[2 * 2 + cm] + (cm ? wxp[2].y : wxp[2].x);
                float vo = acc[3][j] + slot[3 * 2 + cm] + (cm ? wxp[3].y : wxp[3].x);
                float ii = sigmoid_fast(vi);
                float gg = tanh_fast(vg);
                float ff = sigmoid_fast(vf);
                float oo = sigmoid_fast(vo);
                float cn = ff * c_reg[cm] + ii * gg;
                c_reg[cm] = cn;
                float h = oo * tanh_fast(cn);
                int idx = brow * HID + col;
                h_out[idx] = h;
                __nv_bfloat16 hi, lo;
                split_bf16(h, hi, lo);
                g_hhi[cb][idx] = hi;
                g_hlo[cb][idx] = lo;
                if (t == T_STEPS - 1) {
                    size_t base = (size_t)T_STEPS * BATCH * HID;
                    out_base[base + idx] = h;
                    out_base[base + BATCH * HID + idx] = cn;
                }
            }
        }

        // device-wide barrier: per-CTA flag slots (R9, proven)
        if (t < T_STEPS - 1) {
            __threadfence();
            __syncthreads();
            if (tid == 0)
                asm volatile("st.global.cg.u32 [%0], %1;"
                             :: "l"(&g_arrive[blockIdx.x * 8]), "r"(t + 1));
            unsigned target = t + 1;
            bool ok;
            do {
                unsigned v = target;
                if (tid < NCTA)
                    asm volatile("ld.global.cg.u32 %0, [%1];"
                                 : "=r"(v) : "l"(&g_arrive[tid * 8]));
                ok = (v >= target);
            } while (!__syncthreads_and(ok));
            __threadfence();
        }
    }

    // cleanup for graph replay (after ALL CTAs complete)
    if (tid == 0) {
        __threadfence();
        atomicAdd(&g_bar, 1u);
        if (blockIdx.x == 0) {
            while (atomicAdd(&g_bar, 0u) < NCTA) __nanosleep(100);
            for (int i = 0; i < NCTA; i++) g_arrive[i * 8] = 0;
            __threadfence();
            g_bar = 0;
        }
    }
}

extern "C" void kernel_launch(void* const* d_in, const int* in_sizes, int n_in,
                              void* d_out, int out_size)
{
    const float* x    = (const float*)d_in[0];
    const float* Wk   = (const float*)d_in[1];
    const float* Rk   = (const float*)d_in[2];
    const float* bias = (const float*)d_in[3];
    float* out = (float*)d_out;

    cudaFuncSetAttribute(lstm_persistent,
                         cudaFuncAttributeMaxDynamicSharedMemorySize, SMEM_PERS);
    cudaFuncSetAttribute(wx_mma,
                         cudaFuncAttributeMaxDynamicSharedMemorySize, WX_SMEM);

    size_t nx = (size_t)T_STEPS * BATCH * IN_DIM;
    convert_x<<<(unsigned)((nx + 255) / 256), 256>>>(x);
    convert_W<<<dim3(GATES / 32, IN_DIM / 32), dim3(32, 8)>>>(Wk);
    convert_R<<<dim3(GATES / 32, HID / 32), dim3(32, 8)>>>(Rk);

    wx_mma<<<dim3(GATES / 128, (T_STEPS * BATCH) / 128), 256, WX_SMEM>>>(bias);

    lstm_persistent<<<NCTA, 256, SMEM_PERS>>>(out);
}

// round 13
// speedup vs baseline: 2.0563x; 2.0563x over previous
#include <cuda_runtime.h>
#include <cuda_bf16.h>
#include <cuda_fp16.h>
#include <math.h>
#include <stdint.h>

#define T_STEPS 512
#define BATCH   64
#define IN_DIM  1024
#define HID     1024
#define GATES   4096   // 4*HID, gate order i,g,f,o
#define NCTA    128

// ---------------- device scratch ----------------
__device__ float g_wx[(size_t)T_STEPS * BATCH * GATES];   // 512 MB
__device__ unsigned g_arrive[NCTA * 8];                   // 32B-strided per-CTA step flags
__device__ unsigned g_bar;                                // end-of-launch cleanup

__device__ __nv_bfloat16 g_xhi[(size_t)T_STEPS * BATCH * IN_DIM];
__device__ __nv_bfloat16 g_xlo[(size_t)T_STEPS * BATCH * IN_DIM];
__device__ __nv_bfloat16 g_Wthi[(size_t)GATES * IN_DIM];   // transposed [N][K]
__device__ __nv_bfloat16 g_Wtlo[(size_t)GATES * IN_DIM];
__device__ __half g_Rf[(size_t)GATES * HID];               // fp16 transposed [N][K]
__device__ __half g_hf[2][BATCH * HID];                    // fp16 ping-pong h

// ---------------- helpers ----------------
__device__ __forceinline__ void mma16816bf(float* c, const uint32_t* a, const uint32_t* b)
{
    asm volatile(
        "mma.sync.aligned.m16n8k16.row.col.f32.bf16.bf16.f32 "
        "{%0,%1,%2,%3}, {%4,%5,%6,%7}, {%8,%9}, {%0,%1,%2,%3};"
        : "+f"(c[0]), "+f"(c[1]), "+f"(c[2]), "+f"(c[3])
        : "r"(a[0]), "r"(a[1]), "r"(a[2]), "r"(a[3]), "r"(b[0]), "r"(b[1]));
}

__device__ __forceinline__ void mma16816h(float* c, const uint32_t* a, const uint32_t* b)
{
    asm volatile(
        "mma.sync.aligned.m16n8k16.row.col.f32.f16.f16.f32 "
        "{%0,%1,%2,%3}, {%4,%5,%6,%7}, {%8,%9}, {%0,%1,%2,%3};"
        : "+f"(c[0]), "+f"(c[1]), "+f"(c[2]), "+f"(c[3])
        : "r"(a[0]), "r"(a[1]), "r"(a[2]), "r"(a[3]), "r"(b[0]), "r"(b[1]));
}

__device__ __forceinline__ void split_bf16(float v, __nv_bfloat16& hi, __nv_bfloat16& lo)
{
    hi = __float2bfloat16_rn(v);
    lo = __float2bfloat16_rn(v - __bfloat162float(hi));
}

__device__ __forceinline__ float tanh_fast(float x)
{
    float y;
    asm("tanh.approx.f32 %0, %1;" : "=f"(y) : "f"(x));
    return y;
}
__device__ __forceinline__ float sigmoid_fast(float x)
{
    return 0.5f * tanh_fast(0.5f * x) + 0.5f;
}

__device__ __forceinline__ float2 ldcg_f2(const float* p)
{
    float2 v;
    asm volatile("ld.global.cg.v2.f32 {%0,%1}, [%2];" : "=f"(v.x), "=f"(v.y) : "l"(p));
    return v;
}

// ---------------- conversion kernels ----------------
__global__ void convert_x(const float* __restrict__ x)
{
    size_t i = (size_t)blockIdx.x * blockDim.x + threadIdx.x;
    if (i < (size_t)T_STEPS * BATCH * IN_DIM) {
        __nv_bfloat16 hi, lo;
        split_bf16(x[i], hi, lo);
        g_xhi[i] = hi;
        g_xlo[i] = lo;
    }
}

__global__ void convert_W(const float* __restrict__ src)
{
    __shared__ float tile[32][33];
    int n0 = blockIdx.x * 32, k0 = blockIdx.y * 32;
    int tx = threadIdx.x, ty = threadIdx.y;
#pragma unroll
    for (int i = 0; i < 32; i += 8)
        tile[ty + i][tx] = src[(size_t)(k0 + ty + i) * GATES + n0 + tx];
    __syncthreads();
#pragma unroll
    for (int i = 0; i < 32; i += 8) {
        float v = tile[tx][ty + i];
        size_t o = (size_t)(n0 + ty + i) * IN_DIM + k0 + tx;
        __nv_bfloat16 hi, lo;
        split_bf16(v, hi, lo);
        g_Wthi[o] = hi;
        g_Wtlo[o] = lo;
    }
}

// src [K=1024][N=4096] -> g_Rf [N][K] fp16 (transposed)
__global__ void convert_R(const float* __restrict__ src)
{
    __shared__ float tile[32][33];
    int n0 = blockIdx.x * 32, k0 = blockIdx.y * 32;
    int tx = threadIdx.x, ty = threadIdx.y;
#pragma unroll
    for (int i = 0; i < 32; i += 8)
        tile[ty + i][tx] = src[(size_t)(k0 + ty + i) * GATES + n0 + tx];
    __syncthreads();
#pragma unroll
    for (int i = 0; i < 32; i += 8) {
        float v = tile[tx][ty + i];
        g_Rf[(size_t)(n0 + ty + i) * HID + k0 + tx] = __float2half_rn(v);
    }
}

// ---------------- wx GEMM: cp.async double-buffered split-bf16 (proven) -------
#define WXS 40
#define WXC (128 * WXS)
#define WX_SMEM (2 * 4 * WXC * 2)       // 81920 B

__device__ __forceinline__ void wx_stage(uint32_t smb, size_t m0, int n0,
                                         int k0, int b, int tid)
{
    const __nv_bfloat16* srcs[4];
    srcs[0] = g_xhi;  srcs[1] = g_xlo;  srcs[2] = g_Wthi;  srcs[3] = g_Wtlo;
#pragma unroll
    for (int arr = 0; arr < 4; arr++) {
        size_t base = (arr < 2) ? m0 : (size_t)n0;
#pragma unroll
        for (int rep = 0; rep < 2; rep++) {
            int id = tid + rep * 256;
            int row = id >> 2, seg = id & 3;
            const __nv_bfloat16* src = srcs[arr]
                + (base + row) * IN_DIM + k0 + seg * 8;
            uint32_t dst = smb + (uint32_t)(((b * 4 + arr) * WXC
                                             + row * WXS + seg * 8) * 2);
            asm volatile("cp.async.cg.shared.global [%0], [%1], 16;"
                         :: "r"(dst), "l"(src));
        }
    }
    asm volatile("cp.async.commit_group;");
}

__global__ __launch_bounds__(256) void wx_mma(const float* __restrict__ bias)
{
    extern __shared__ __align__(16) unsigned char wxsm[];
    __nv_bfloat16* S = (__nv_bfloat16*)wxsm;
    uint32_t smb = (uint32_t)__cvta_generic_to_shared(S);

    int tid  = threadIdx.x;
    int lane = tid & 31, w = tid >> 5;
    int g = lane >> 2, tq = lane & 3;
    size_t m0 = (size_t)blockIdx.y * 128;
    int n0 = blockIdx.x * 128;
    int wm = w & 1, wn = w >> 1;

    float acc[4][4][4];
#pragma unroll
    for (int mt = 0; mt < 4; mt++)
#pragma unroll
        for (int nt = 0; nt < 4; nt++)
#pragma unroll
            for (int r = 0; r < 4; r++) acc[mt][nt][r] = 0.f;

    wx_stage(smb, m0, n0, 0, 0, tid);

    for (int kc = 0; kc < 32; kc++) {
        int cur = kc & 1;
        if (kc < 31) {
            wx_stage(smb, m0, n0, (kc + 1) * 32, cur ^ 1, tid);
            asm volatile("cp.async.wait_group 1;");
        } else {
            asm volatile("cp.async.wait_group 0;");
        }
        __syncthreads();

        const __nv_bfloat16* Ah = S + (cur * 4 + 0) * WXC;
        const __nv_bfloat16* Al = S + (cur * 4 + 1) * WXC;
        const __nv_bfloat16* Bh = S + (cur * 4 + 2) * WXC;
        const __nv_bfloat16* Bl = S + (cur * 4 + 3) * WXC;

#pragma unroll
        for (int ks = 0; ks < 2; ks++) {
            int ko = ks * 16;
            uint32_t bh[4][2], bl[4][2];
#pragma unroll
            for (int nt = 0; nt < 4; nt++) {
                int r = wn * 32 + nt * 8 + g;
                bh[nt][0] = *(const uint32_t*)&Bh[r * WXS + ko + 2 * tq];
                bh[nt][1] = *(const uint32_t*)&Bh[r * WXS + ko + 2 * tq + 8];
                bl[nt][0] = *(const uint32_t*)&Bl[r * WXS + ko + 2 * tq];
                bl[nt][1] = *(const uint32_t*)&Bl[r * WXS + ko + 2 * tq + 8];
            }
#pragma unroll
            for (int mt = 0; mt < 4; mt++) {
                int r0 = wm * 64 + mt * 16 + g, r1 = r0 + 8;
                uint32_t ah[4], al[4];
                ah[0] = *(const uint32_t*)&Ah[r0 * WXS + ko + 2 * tq];
                ah[1] = *(const uint32_t*)&Ah[r1 * WXS + ko + 2 * tq];
                ah[2] = *(const uint32_t*)&Ah[r0 * WXS + ko + 2 * tq + 8];
                ah[3] = *(const uint32_t*)&Ah[r1 * WXS + ko + 2 * tq + 8];
                al[0] = *(const uint32_t*)&Al[r0 * WXS + ko + 2 * tq];
                al[1] = *(const uint32_t*)&Al[r1 * WXS + ko + 2 * tq];
                al[2] = *(const uint32_t*)&Al[r0 * WXS + ko + 2 * tq + 8];
                al[3] = *(const uint32_t*)&Al[r1 * WXS + ko + 2 * tq + 8];
#pragma unroll
                for (int nt = 0; nt < 4; nt++) mma16816bf(acc[mt][nt], ah, bh[nt]);
#pragma unroll
                for (int nt = 0; nt < 4; nt++) mma16816bf(acc[mt][nt], ah, bl[nt]);
#pragma unroll
                for (int nt = 0; nt < 4; nt++) mma16816bf(acc[mt][nt], al, bh[nt]);
            }
        }
        __syncthreads();
    }

#pragma unroll
    for (int mt = 0; mt < 4; mt++) {
        size_t row = m0 + wm * 64 + mt * 16 + g;
#pragma unroll
        for (int nt = 0; nt < 4; nt++) {
            int col = n0 + wn * 32 + nt * 8 + 2 * tq;
            g_wx[row * GATES + col]           = acc[mt][nt][0] + bias[col];
            g_wx[row * GATES + col + 1]       = acc[mt][nt][1] + bias[col + 1];
            g_wx[(row + 8) * GATES + col]     = acc[mt][nt][2] + bias[col];
            g_wx[(row + 8) * GATES + col + 1] = acc[mt][nt][3] + bias[col + 1];
        }
    }
}

// ---------------- persistent LSTM recurrence v7 ----------------
// R9 skeleton (proven best): per-warp cp.async staging, flag-array barrier —
// but fp16 SINGLE-PASS numerics: 1 mma pass (was 3), half the h traffic,
// half the staging. R slice fp16 in smem (66 KB).
#define RSTR 1032                                  // fp16 elems per R row (1024+8)
#define HSTR 72                                    // fp16 elems per staged h row
#define HBUF_B (16 * HSTR * 2)                     // 2304 B per (warp,buf)
#define H_REGION (16 * HBUF_B)                     // 8 warps x 2 bufs = 36864 B
#define RED_OFF (32 * RSTR * 2 + H_REGION)         // 66048 + 36864
#define SMEM_PERS (RED_OFF + 2 * 128 * 9 * 4)      // +9216 B reduction

__device__ __forceinline__ void stage_warp(uint32_t hbase_sm,
                                           const __half* hsrc,
                                           int w, int grp, int wm,
                                           int kc, int b, int lane)
{
#pragma unroll
    for (int s = 0; s < 4; s++) {
        int id = s * 32 + lane;                    // 0..127
        int row = id >> 3, segk = id & 7;
        const __half* src = hsrc
            + (size_t)(wm * 16 + row) * HID + grp * 512 + kc * 64 + segk * 8;
        uint32_t dst = hbase_sm
            + (uint32_t)((w * 2 + b) * HBUF_B + row * (HSTR * 2) + segk * 16);
        asm volatile("cp.async.cg.shared.global [%0], [%1], 16;" :: "r"(dst), "l"(src));
    }
    asm volatile("cp.async.commit_group;");
}

__global__ __launch_bounds__(256) void lstm_persistent(float* __restrict__ out_base)
{
    extern __shared__ __align__(16) unsigned char smem_raw[];
    __half* Rf = (__half*)smem_raw;
    __half* Hbase = Rf + 32 * RSTR;
    float* Red = (float*)(smem_raw + RED_OFF);
    uint32_t hbase_sm = (uint32_t)__cvta_generic_to_shared(Hbase);

    const int tid  = threadIdx.x;
    const int lane = tid & 31, w = tid >> 5;
    const int g = lane >> 2, tq = lane & 3;
    const int grp = w >> 2, wm = w & 3;
    const int hc0 = blockIdx.x * 8;

    // load fp16 R slice into smem once: rows 0..31 = gate*8 + c8
    for (int rep = 0; rep < 16; rep++) {
        int id = rep * 256 + tid;
        int row = id >> 7, seg = id & 127;
        size_t src = (size_t)((row >> 3) * HID + hc0 + (row & 7)) * HID + seg * 8;
        *(uint4*)&Rf[row * RSTR + seg * 8] = *(const uint4*)&g_Rf[src];
    }
    __syncthreads();

    float c_reg[2] = {0.f, 0.f};

    for (int t = 0; t < T_STEPS; t++) {
        // prefetch this group's wx half (DRAM, independent of h)
        float2 wxp[4];
        {
            const float* wx_t = g_wx + (size_t)t * BATCH * GATES;
            int brow = wm * 16 + g + grp * 8;
#pragma unroll
            for (int gate = 0; gate < 4; gate++)
                wxp[gate] = ldcg_f2(wx_t + (size_t)brow * GATES + gate * HID + hc0 + 2 * tq);
        }

        float acc[4][4];
#pragma unroll
        for (int nt = 0; nt < 4; nt++)
#pragma unroll
            for (int r = 0; r < 4; r++) acc[nt][r] = 0.f;

        if (t > 0) {
            const __half* hsrc = g_hf[(t - 1) & 1];

            stage_warp(hbase_sm, hsrc, w, grp, wm, 0, 0, lane);
            stage_warp(hbase_sm, hsrc, w, grp, wm, 1, 1, lane);

            for (int kc = 0; kc < 8; kc++) {
                int cur = kc & 1;
                if (kc < 6) asm volatile("cp.async.wait_group 1;");
                else        asm volatile("cp.async.wait_group 0;");

                const __half* HC = (const __half*)
                    ((const unsigned char*)Hbase + (w * 2 + cur) * HBUF_B);
#pragma unroll
                for (int kt = 0; kt < 4; kt++) {
                    int ko = kt * 16 + 2 * tq;
                    uint32_t ah[4];
                    ah[0] = *(const uint32_t*)&HC[g * HSTR + ko];
                    ah[1] = *(const uint32_t*)&HC[(g + 8) * HSTR + ko];
                    ah[2] = *(const uint32_t*)&HC[g * HSTR + ko + 8];
                    ah[3] = *(const uint32_t*)&HC[(g + 8) * HSTR + ko + 8];
                    int kR = grp * 512 + kc * 64 + kt * 16 + 2 * tq;
                    uint32_t bf[4][2];
#pragma unroll
                    for (int nt = 0; nt < 4; nt++) {
                        int rr = nt * 8 + g;
                        bf[nt][0] = *(const uint32_t*)&Rf[rr * RSTR + kR];
                        bf[nt][1] = *(const uint32_t*)&Rf[rr * RSTR + kR + 8];
                    }
#pragma unroll
                    for (int nt = 0; nt < 4; nt++) mma16816h(acc[nt], ah, bf[nt]);
                }
                if (kc + 2 < 8)
                    stage_warp(hbase_sm, hsrc, w, grp, wm, kc + 2, cur, lane);
            }
        }

        // cross-group exchange: ship the jj-half this group does NOT own
        {
            float* slot = Red + ((grp ^ 1) * 128 + wm * 32 + lane) * 9;
            int jbase = (grp == 1) ? 0 : 2;
#pragma unroll
            for (int nt = 0; nt < 4; nt++) {
                slot[nt * 2 + 0] = acc[nt][jbase + 0];
                slot[nt * 2 + 1] = acc[nt][jbase + 1];
            }
        }
        __syncthreads();

        {
            const float* slot = Red + (grp * 128 + wm * 32 + lane) * 9;
            int jbase = grp * 2;
            float* h_out = out_base + (size_t)t * BATCH * HID;
            int cb = t & 1;
#pragma unroll
            for (int cm = 0; cm < 2; cm++) {
                int j = jbase + cm;
                int brow = wm * 16 + g + grp * 8;
                int col  = hc0 + 2 * tq + cm;
                float vi = acc[0][j] + slot[0 * 2 + cm] + (cm ? wxp[0].y : wxp[0].x);
                float vg = acc[1][j] + slot[1 * 2 + cm] + (cm ? wxp[1].y : wxp[1].x);
                float vf = acc[2][j] + slot[2 * 2 + cm] + (cm ? wxp[2].y : wxp[2].x);
                float vo = acc[3][j] + slot[3 * 2 + cm] + (cm ? wxp[3].y : wxp[3].x);
                float ii = sigmoid_fast(vi);
                float gg = tanh_fast(vg);
                float ff = sigmoid_fast(vf);
                float oo = sigmoid_fast(vo);
                float cn = ff * c_reg[cm] + ii * gg;
                c_reg[cm] = cn;
                float h = oo * tanh_fast(cn);
                int idx = brow * HID + col;
                h_out[idx] = h;
                g_hf[cb][idx] = __float2half_rn(h);
                if (t == T_STEPS - 1) {
                    size_t base = (size_t)T_STEPS * BATCH * HID;
                    out_base[base + idx] = h;
                    out_base[base + BATCH * HID + idx] = cn;
                }
            }
        }

        // device-wide barrier: per-CTA flag slots (R9, proven)
        if (t < T_STEPS - 1) {
            __threadfence();
            __syncthreads();
            if (tid == 0)
                asm volatile("st.global.cg.u32 [%0], %1;"
                             :: "l"(&g_arrive[blockIdx.x * 8]), "r"(t + 1));
            unsigned target = t + 1;
            bool ok;
            do {
                unsigned v = target;
                if (tid < NCTA)
                    asm volatile("ld.global.cg.u32 %0, [%1];"
                                 : "=r"(v) : "l"(&g_arrive[tid * 8]));
                ok = (v >= target);
            } while (!__syncthreads_and(ok));
            __threadfence();
        }
    }

    // cleanup for graph replay (after ALL CTAs complete)
    if (tid == 0) {
        __threadfence();
        atomicAdd(&g_bar, 1u);
        if (blockIdx.x == 0) {
            while (atomicAdd(&g_bar, 0u) < NCTA) __nanosleep(100);
            for (int i = 0; i < NCTA; i++) g_arrive[i * 8] = 0;
            __threadfence();
            g_bar = 0;
        }
    }
}

extern "C" void kernel_launch(void* const* d_in, const int* in_sizes, int n_in,
                              void* d_out, int out_size)
{
    const float* x    = (const float*)d_in[0];
    const float* Wk   = (const float*)d_in[1];
    const float* Rk   = (const float*)d_in[2];
    const float* bias = (const float*)d_in[3];
    float* out = (float*)d_out;

    cudaFuncSetAttribute(lstm_persistent,
                         cudaFuncAttributeMaxDynamicSharedMemorySize, SMEM_PERS);
    cudaFuncSetAttribute(wx_mma,
                         cudaFuncAttributeMaxDynamicSharedMemorySize, WX_SMEM);

    size_t nx = (size_t)T_STEPS * BATCH * IN_DIM;
    convert_x<<<(unsigned)((nx + 255) / 256), 256>>>(x);
    convert_W<<<dim3(GATES / 32, IN_DIM / 32), dim3(32, 8)>>>(Wk);
    convert_R<<<dim3(GATES / 32, HID / 32), dim3(32, 8)>>>(Rk);

    wx_mma<<<dim3(GATES / 128, (T_STEPS * BATCH) / 128), 256, WX_SMEM>>>(bias);

    lstm_persistent<<<NCTA, 256, SMEM_PERS>>>(out);
}

// round 14
// speedup vs baseline: 2.5295x; 1.2301x over previous
#include <cuda_runtime.h>
#include <cuda_bf16.h>
#include <cuda_fp16.h>
#include <math.h>
#include <stdint.h>

#define T_STEPS 512
#define BATCH   64
#define IN_DIM  1024
#define HID     1024
#define GATES   4096   // 4*HID, gate order i,g,f,o
#define NCTA    128

// ---------------- device scratch ----------------
__device__ float g_wx[(size_t)T_STEPS * BATCH * GATES];   // 512 MB
__device__ unsigned g_arrive[NCTA * 8];                   // 32B-strided per-CTA step flags
__device__ unsigned g_bar;                                // end-of-launch cleanup

__device__ __half g_xf[(size_t)T_STEPS * BATCH * IN_DIM]; // fp16 x
__device__ __half g_Wf[(size_t)GATES * IN_DIM];           // fp16 W transposed [N][K]
__device__ __half g_Rf[(size_t)GATES * HID];              // fp16 R transposed [N][K]
__device__ __half g_hf[2][BATCH * HID];                   // fp16 ping-pong h

// ---------------- helpers ----------------
__device__ __forceinline__ void mma16816h(float* c, const uint32_t* a, const uint32_t* b)
{
    asm volatile(
        "mma.sync.aligned.m16n8k16.row.col.f32.f16.f16.f32 "
        "{%0,%1,%2,%3}, {%4,%5,%6,%7}, {%8,%9}, {%0,%1,%2,%3};"
        : "+f"(c[0]), "+f"(c[1]), "+f"(c[2]), "+f"(c[3])
        : "r"(a[0]), "r"(a[1]), "r"(a[2]), "r"(a[3]), "r"(b[0]), "r"(b[1]));
}

__device__ __forceinline__ float tanh_fast(float x)
{
    float y;
    asm("tanh.approx.f32 %0, %1;" : "=f"(y) : "f"(x));
    return y;
}
__device__ __forceinline__ float sigmoid_fast(float x)
{
    return 0.5f * tanh_fast(0.5f * x) + 0.5f;
}

__device__ __forceinline__ float2 ldcg_f2(const float* p)
{
    float2 v;
    asm volatile("ld.global.cg.v2.f32 {%0,%1}, [%2];" : "=f"(v.x), "=f"(v.y) : "l"(p));
    return v;
}

// ---------------- conversion kernels ----------------
__global__ void convert_x(const float* __restrict__ x)
{
    size_t i = (size_t)blockIdx.x * blockDim.x + threadIdx.x;
    if (i < (size_t)T_STEPS * BATCH * IN_DIM)
        g_xf[i] = __float2half_rn(x[i]);
}

// src [K=1024][N=4096] -> g_Wf [N][K] fp16 (transposed)
__global__ void convert_W(const float* __restrict__ src)
{
    __shared__ float tile[32][33];
    int n0 = blockIdx.x * 32, k0 = blockIdx.y * 32;
    int tx = threadIdx.x, ty = threadIdx.y;
#pragma unroll
    for (int i = 0; i < 32; i += 8)
        tile[ty + i][tx] = src[(size_t)(k0 + ty + i) * GATES + n0 + tx];
    __syncthreads();
#pragma unroll
    for (int i = 0; i < 32; i += 8)
        g_Wf[(size_t)(n0 + ty + i) * IN_DIM + k0 + tx] = __float2half_rn(tile[tx][ty + i]);
}

// src [K=1024][N=4096] -> g_Rf [N][K] fp16 (transposed)
__global__ void convert_R(const float* __restrict__ src)
{
    __shared__ float tile[32][33];
    int n0 = blockIdx.x * 32, k0 = blockIdx.y * 32;
    int tx = threadIdx.x, ty = threadIdx.y;
#pragma unroll
    for (int i = 0; i < 32; i += 8)
        tile[ty + i][tx] = src[(size_t)(k0 + ty + i) * GATES + n0 + tx];
    __syncthreads();
#pragma unroll
    for (int i = 0; i < 32; i += 8)
        g_Rf[(size_t)(n0 + ty + i) * HID + k0 + tx] = __float2half_rn(tile[tx][ty + i]);
}

// ---------------- wx GEMM: fp16 single-pass, cp.async double-buffered ---------
#define WXS 40
#define WXC (128 * WXS)                 // elems per array per buffer
#define WX_SMEM (2 * 2 * WXC * 2)       // 2 bufs x (A,B) x fp16 = 40960 B

__device__ __forceinline__ void wx_stage(uint32_t smb, size_t m0, int n0,
                                         int k0, int b, int tid)
{
#pragma unroll
    for (int arr = 0; arr < 2; arr++) {
        const __half* sp = arr ? g_Wf : g_xf;
        size_t base = arr ? (size_t)n0 : m0;
#pragma unroll
        for (int rep = 0; rep < 2; rep++) {
            int id = tid + rep * 256;
            int row = id >> 2, seg = id & 3;
            const __half* src = sp + (base + row) * IN_DIM + k0 + seg * 8;
            uint32_t dst = smb + (uint32_t)(((b * 2 + arr) * WXC
                                             + row * WXS + seg * 8) * 2);
            asm volatile("cp.async.cg.shared.global [%0], [%1], 16;"
                         :: "r"(dst), "l"(src));
        }
    }
    asm volatile("cp.async.commit_group;");
}

__global__ __launch_bounds__(256) void wx_mma(const float* __restrict__ bias)
{
    extern __shared__ __align__(16) unsigned char wxsm[];
    __half* S = (__half*)wxsm;
    uint32_t smb = (uint32_t)__cvta_generic_to_shared(S);

    int tid  = threadIdx.x;
    int lane = tid & 31, w = tid >> 5;
    int g = lane >> 2, tq = lane & 3;
    size_t m0 = (size_t)blockIdx.y * 128;
    int n0 = blockIdx.x * 128;
    int wm = w & 1, wn = w >> 1;

    float acc[4][4][4];
#pragma unroll
    for (int mt = 0; mt < 4; mt++)
#pragma unroll
        for (int nt = 0; nt < 4; nt++)
#pragma unroll
            for (int r = 0; r < 4; r++) acc[mt][nt][r] = 0.f;

    wx_stage(smb, m0, n0, 0, 0, tid);

    for (int kc = 0; kc < 32; kc++) {
        int cur = kc & 1;
        if (kc < 31) {
            wx_stage(smb, m0, n0, (kc + 1) * 32, cur ^ 1, tid);
            asm volatile("cp.async.wait_group 1;");
        } else {
            asm volatile("cp.async.wait_group 0;");
        }
        __syncthreads();

        const __half* A = S + (cur * 2 + 0) * WXC;
        const __half* B = S + (cur * 2 + 1) * WXC;

#pragma unroll
        for (int ks = 0; ks < 2; ks++) {
            int ko = ks * 16;
            uint32_t bf[4][2];
#pragma unroll
            for (int nt = 0; nt < 4; nt++) {
                int r = wn * 32 + nt * 8 + g;
                bf[nt][0] = *(const uint32_t*)&B[r * WXS + ko + 2 * tq];
                bf[nt][1] = *(const uint32_t*)&B[r * WXS + ko + 2 * tq + 8];
            }
#pragma unroll
            for (int mt = 0; mt < 4; mt++) {
                int r0 = wm * 64 + mt * 16 + g, r1 = r0 + 8;
                uint32_t af[4];
                af[0] = *(const uint32_t*)&A[r0 * WXS + ko + 2 * tq];
                af[1] = *(const uint32_t*)&A[r1 * WXS + ko + 2 * tq];
                af[2] = *(const uint32_t*)&A[r0 * WXS + ko + 2 * tq + 8];
                af[3] = *(const uint32_t*)&A[r1 * WXS + ko + 2 * tq + 8];
#pragma unroll
                for (int nt = 0; nt < 4; nt++) mma16816h(acc[mt][nt], af, bf[nt]);
            }
        }
        __syncthreads();
    }

#pragma unroll
    for (int mt = 0; mt < 4; mt++) {
        size_t row = m0 + wm * 64 + mt * 16 + g;
#pragma unroll
        for (int nt = 0; nt < 4; nt++) {
            int col = n0 + wn * 32 + nt * 8 + 2 * tq;
            g_wx[row * GATES + col]           = acc[mt][nt][0] + bias[col];
            g_wx[row * GATES + col + 1]       = acc[mt][nt][1] + bias[col + 1];
            g_wx[(row + 8) * GATES + col]     = acc[mt][nt][2] + bias[col];
            g_wx[(row + 8) * GATES + col + 1] = acc[mt][nt][3] + bias[col + 1];
        }
    }
}

// ---------------- persistent LSTM recurrence (R13, proven) ----------------
#define RSTR 1032                                  // fp16 elems per R row (1024+8)
#define HSTR 72                                    // fp16 elems per staged h row
#define HBUF_B (16 * HSTR * 2)                     // 2304 B per (warp,buf)
#define H_REGION (16 * HBUF_B)                     // 8 warps x 2 bufs = 36864 B
#define RED_OFF (32 * RSTR * 2 + H_REGION)
#define SMEM_PERS (RED_OFF + 2 * 128 * 9 * 4)

__device__ __forceinline__ void stage_warp(uint32_t hbase_sm,
                                           const __half* hsrc,
                                           int w, int grp, int wm,
                                           int kc, int b, int lane)
{
#pragma unroll
    for (int s = 0; s < 4; s++) {
        int id = s * 32 + lane;                    // 0..127
        int row = id >> 3, segk = id & 7;
        const __half* src = hsrc
            + (size_t)(wm * 16 + row) * HID + grp * 512 + kc * 64 + segk * 8;
        uint32_t dst = hbase_sm
            + (uint32_t)((w * 2 + b) * HBUF_B + row * (HSTR * 2) + segk * 16);
        asm volatile("cp.async.cg.shared.global [%0], [%1], 16;" :: "r"(dst), "l"(src));
    }
    asm volatile("cp.async.commit_group;");
}

__global__ __launch_bounds__(256) void lstm_persistent(float* __restrict__ out_base)
{
    extern __shared__ __align__(16) unsigned char smem_raw[];
    __half* Rf = (__half*)smem_raw;
    __half* Hbase = Rf + 32 * RSTR;
    float* Red = (float*)(smem_raw + RED_OFF);
    uint32_t hbase_sm = (uint32_t)__cvta_generic_to_shared(Hbase);

    const int tid  = threadIdx.x;
    const int lane = tid & 31, w = tid >> 5;
    const int g = lane >> 2, tq = lane & 3;
    const int grp = w >> 2, wm = w & 3;
    const int hc0 = blockIdx.x * 8;

    // load fp16 R slice into smem once: rows 0..31 = gate*8 + c8
    for (int rep = 0; rep < 16; rep++) {
        int id = rep * 256 + tid;
        int row = id >> 7, seg = id & 127;
        size_t src = (size_t)((row >> 3) * HID + hc0 + (row & 7)) * HID + seg * 8;
        *(uint4*)&Rf[row * RSTR + seg * 8] = *(const uint4*)&g_Rf[src];
    }
    __syncthreads();

    float c_reg[2] = {0.f, 0.f};

    for (int t = 0; t < T_STEPS; t++) {
        // prefetch this group's wx half (DRAM, independent of h)
        float2 wxp[4];
        {
            const float* wx_t = g_wx + (size_t)t * BATCH * GATES;
            int brow = wm * 16 + g + grp * 8;
#pragma unroll
            for (int gate = 0; gate < 4; gate++)
                wxp[gate] = ldcg_f2(wx_t + (size_t)brow * GATES + gate * HID + hc0 + 2 * tq);
        }

        float acc[4][4];
#pragma unroll
        for (int nt = 0; nt < 4; nt++)
#pragma unroll
            for (int r = 0; r < 4; r++) acc[nt][r] = 0.f;

        if (t > 0) {
            const __half* hsrc = g_hf[(t - 1) & 1];

            stage_warp(hbase_sm, hsrc, w, grp, wm, 0, 0, lane);
            stage_warp(hbase_sm, hsrc, w, grp, wm, 1, 1, lane);

            for (int kc = 0; kc < 8; kc++) {
                int cur = kc & 1;
                if (kc < 6) asm volatile("cp.async.wait_group 1;");
                else        asm volatile("cp.async.wait_group 0;");

                const __half* HC = (const __half*)
                    ((const unsigned char*)Hbase + (w * 2 + cur) * HBUF_B);
#pragma unroll
                for (int kt = 0; kt < 4; kt++) {
                    int ko = kt * 16 + 2 * tq;
                    uint32_t ah[4];
                    ah[0] = *(const uint32_t*)&HC[g * HSTR + ko];
                    ah[1] = *(const uint32_t*)&HC[(g + 8) * HSTR + ko];
                    ah[2] = *(const uint32_t*)&HC[g * HSTR + ko + 8];
                    ah[3] = *(const uint32_t*)&HC[(g + 8) * HSTR + ko + 8];
                    int kR = grp * 512 + kc * 64 + kt * 16 + 2 * tq;
                    uint32_t bf[4][2];
#pragma unroll
                    for (int nt = 0; nt < 4; nt++) {
                        int rr = nt * 8 + g;
                        bf[nt][0] = *(const uint32_t*)&Rf[rr * RSTR + kR];
                        bf[nt][1] = *(const uint32_t*)&Rf[rr * RSTR + kR + 8];
                    }
#pragma unroll
                    for (int nt = 0; nt < 4; nt++) mma16816h(acc[nt], ah, bf[nt]);
                }
                if (kc + 2 < 8)
                    stage_warp(hbase_sm, hsrc, w, grp, wm, kc + 2, cur, lane);
            }
        }

        // cross-group exchange: ship the jj-half this group does NOT own
        {
            float* slot = Red + ((grp ^ 1) * 128 + wm * 32 + lane) * 9;
            int jbase = (grp == 1) ? 0 : 2;
#pragma unroll
            for (int nt = 0; nt < 4; nt++) {
                slot[nt * 2 + 0] = acc[nt][jbase + 0];
                slot[nt * 2 + 1] = acc[nt][jbase + 1];
            }
        }
        __syncthreads();

        {
            const float* slot = Red + (grp * 128 + wm * 32 + lane) * 9;
            int jbase = grp * 2;
            float* h_out = out_base + (size_t)t * BATCH * HID;
            int cb = t & 1;
#pragma unroll
            for (int cm = 0; cm < 2; cm++) {
                int j = jbase + cm;
                int brow = wm * 16 + g + grp * 8;
                int col  = hc0 + 2 * tq + cm;
                float vi = acc[0][j] + slot[0 * 2 + cm] + (cm ? wxp[0].y : wxp[0].x);
                float vg = acc[1][j] + slot[1 * 2 + cm] + (cm ? wxp[1].y : wxp[1].x);
                float vf = acc[2][j] + slot[2 * 2 + cm] + (cm ? wxp[2].y : wxp[2].x);
                float vo = acc[3][j] + slot[3 * 2 + cm] + (cm ? wxp[3].y : wxp[3].x);
                float ii = sigmoid_fast(vi);
                float gg = tanh_fast(vg);
                float ff = sigmoid_fast(vf);
                float oo = sigmoid_fast(vo);
                float cn = ff * c_reg[cm] + ii * gg;
                c_reg[cm] = cn;
                float h = oo * tanh_fast(cn);
                int idx = brow * HID + col;
                h_out[idx] = h;
                g_hf[cb][idx] = __float2half_rn(h);
                if (t == T_STEPS - 1) {
                    size_t base = (size_t)T_STEPS * BATCH * HID;
                    out_base[base + idx] = h;
                    out_base[base + BATCH * HID + idx] = cn;
                }
            }
        }

        // device-wide barrier: per-CTA flag slots (proven)
        if (t < T_STEPS - 1) {
            __threadfence();
            __syncthreads();
            if (tid == 0)
                asm volatile("st.global.cg.u32 [%0], %1;"
                             :: "l"(&g_arrive[blockIdx.x * 8]), "r"(t + 1));
            unsigned target = t + 1;
            bool ok;
            do {
                unsigned v = target;
                if (tid < NCTA)
                    asm volatile("ld.global.cg.u32 %0, [%1];"
                                 : "=r"(v) : "l"(&g_arrive[tid * 8]));
                ok = (v >= target);
            } while (!__syncthreads_and(ok));
            __threadfence();
        }
    }

    // cleanup for graph replay (after ALL CTAs complete)
    if (tid == 0) {
        __threadfence();
        atomicAdd(&g_bar, 1u);
        if (blockIdx.x == 0) {
            while (atomicAdd(&g_bar, 0u) < NCTA) __nanosleep(100);
            for (int i = 0; i < NCTA; i++) g_arrive[i * 8] = 0;
            __threadfence();
            g_bar = 0;
        }
    }
}

extern "C" void kernel_launch(void* const* d_in, const int* in_sizes, int n_in,
                              void* d_out, int out_size)
{
    const float* x    = (const float*)d_in[0];
    const float* Wk   = (const float*)d_in[1];
    const float* Rk   = (const float*)d_in[2];
    const float* bias = (const float*)d_in[3];
    float* out = (float*)d_out;

    cudaFuncSetAttribute(lstm_persistent,
                         cudaFuncAttributeMaxDynamicSharedMemorySize, SMEM_PERS);
    cudaFuncSetAttribute(wx_mma,
                         cudaFuncAttributeMaxDynamicSharedMemorySize, WX_SMEM);

    size_t nx = (size_t)T_STEPS * BATCH * IN_DIM;
    convert_x<<<(unsigned)((nx + 255) / 256), 256>>>(x);
    convert_W<<<dim3(GATES / 32, IN_DIM / 32), dim3(32, 8)>>>(Wk);
    convert_R<<<dim3(GATES / 32, HID / 32), dim3(32, 8)>>>(Rk);

    wx_mma<<<dim3(GATES / 128, (T_STEPS * BATCH) / 128), 256, WX_SMEM>>>(bias);

    lstm_persistent<<<NCTA, 256, SMEM_PERS>>>(out);
}

// round 15
// speedup vs baseline: 2.6913x; 1.0640x over previous
#include <cuda_runtime.h>
#include <cuda_bf16.h>
#include <cuda_fp16.h>
#include <math.h>
#include <stdint.h>

#define T_STEPS 512
#define BATCH   64
#define IN_DIM  1024
#define HID     1024
#define GATES   4096   // 4*HID, gate order i,g,f,o
#define NCTA    128

// ---------------- device scratch ----------------
__device__ float g_wx[(size_t)T_STEPS * BATCH * GATES];   // 512 MB
__device__ unsigned g_arrive[NCTA * 8];                   // 32B-strided per-CTA step flags
__device__ unsigned g_bar;                                // end-of-launch cleanup

__device__ __half g_xf[(size_t)T_STEPS * BATCH * IN_DIM]; // fp16 x
__device__ __half g_Wf[(size_t)GATES * IN_DIM];           // fp16 W transposed [N][K]
__device__ __half g_Rf[(size_t)GATES * HID];              // fp16 R transposed [N][K]
__device__ __half g_hf[2][BATCH * HID];                   // fp16 ping-pong h

// ---------------- helpers ----------------
__device__ __forceinline__ void mma16816h(float* c, const uint32_t* a, const uint32_t* b)
{
    asm volatile(
        "mma.sync.aligned.m16n8k16.row.col.f32.f16.f16.f32 "
        "{%0,%1,%2,%3}, {%4,%5,%6,%7}, {%8,%9}, {%0,%1,%2,%3};"
        : "+f"(c[0]), "+f"(c[1]), "+f"(c[2]), "+f"(c[3])
        : "r"(a[0]), "r"(a[1]), "r"(a[2]), "r"(a[3]), "r"(b[0]), "r"(b[1]));
}

__device__ __forceinline__ float tanh_fast(float x)
{
    float y;
    asm("tanh.approx.f32 %0, %1;" : "=f"(y) : "f"(x));
    return y;
}
__device__ __forceinline__ float sigmoid_fast(float x)
{
    return 0.5f * tanh_fast(0.5f * x) + 0.5f;
}

__device__ __forceinline__ float ldcg_f(const float* p)
{
    float v;
    asm volatile("ld.global.cg.f32 %0, [%1];" : "=f"(v) : "l"(p));
    return v;
}

// ---------------- conversion kernels ----------------
__global__ void convert_x(const float* __restrict__ x)
{
    size_t i = (size_t)blockIdx.x * blockDim.x + threadIdx.x;
    if (i < (size_t)T_STEPS * BATCH * IN_DIM)
        g_xf[i] = __float2half_rn(x[i]);
}

__global__ void convert_W(const float* __restrict__ src)
{
    __shared__ float tile[32][33];
    int n0 = blockIdx.x * 32, k0 = blockIdx.y * 32;
    int tx = threadIdx.x, ty = threadIdx.y;
#pragma unroll
    for (int i = 0; i < 32; i += 8)
        tile[ty + i][tx] = src[(size_t)(k0 + ty + i) * GATES + n0 + tx];
    __syncthreads();
#pragma unroll
    for (int i = 0; i < 32; i += 8)
        g_Wf[(size_t)(n0 + ty + i) * IN_DIM + k0 + tx] = __float2half_rn(tile[tx][ty + i]);
}

__global__ void convert_R(const float* __restrict__ src)
{
    __shared__ float tile[32][33];
    int n0 = blockIdx.x * 32, k0 = blockIdx.y * 32;
    int tx = threadIdx.x, ty = threadIdx.y;
#pragma unroll
    for (int i = 0; i < 32; i += 8)
        tile[ty + i][tx] = src[(size_t)(k0 + ty + i) * GATES + n0 + tx];
    __syncthreads();
#pragma unroll
    for (int i = 0; i < 32; i += 8)
        g_Rf[(size_t)(n0 + ty + i) * HID + k0 + tx] = __float2half_rn(tile[tx][ty + i]);
}

// ---------------- wx GEMM: fp16 single-pass, cp.async double-buffered (R14) ---
#define WXS 40
#define WXC (128 * WXS)
#define WX_SMEM (2 * 2 * WXC * 2)       // 40960 B

__device__ __forceinline__ void wx_stage(uint32_t smb, size_t m0, int n0,
                                         int k0, int b, int tid)
{
#pragma unroll
    for (int arr = 0; arr < 2; arr++) {
        const __half* sp = arr ? g_Wf : g_xf;
        size_t base = arr ? (size_t)n0 : m0;
#pragma unroll
        for (int rep = 0; rep < 2; rep++) {
            int id = tid + rep * 256;
            int row = id >> 2, seg = id & 3;
            const __half* src = sp + (base + row) * IN_DIM + k0 + seg * 8;
            uint32_t dst = smb + (uint32_t)(((b * 2 + arr) * WXC
                                             + row * WXS + seg * 8) * 2);
            asm volatile("cp.async.cg.shared.global [%0], [%1], 16;"
                         :: "r"(dst), "l"(src));
        }
    }
    asm volatile("cp.async.commit_group;");
}

__global__ __launch_bounds__(256) void wx_mma(const float* __restrict__ bias)
{
    extern __shared__ __align__(16) unsigned char wxsm[];
    __half* S = (__half*)wxsm;
    uint32_t smb = (uint32_t)__cvta_generic_to_shared(S);

    int tid  = threadIdx.x;
    int lane = tid & 31, w = tid >> 5;
    int g = lane >> 2, tq = lane & 3;
    size_t m0 = (size_t)blockIdx.y * 128;
    int n0 = blockIdx.x * 128;
    int wm = w & 1, wn = w >> 1;

    float acc[4][4][4];
#pragma unroll
    for (int mt = 0; mt < 4; mt++)
#pragma unroll
        for (int nt = 0; nt < 4; nt++)
#pragma unroll
            for (int r = 0; r < 4; r++) acc[mt][nt][r] = 0.f;

    wx_stage(smb, m0, n0, 0, 0, tid);

    for (int kc = 0; kc < 32; kc++) {
        int cur = kc & 1;
        if (kc < 31) {
            wx_stage(smb, m0, n0, (kc + 1) * 32, cur ^ 1, tid);
            asm volatile("cp.async.wait_group 1;");
        } else {
            asm volatile("cp.async.wait_group 0;");
        }
        __syncthreads();

        const __half* A = S + (cur * 2 + 0) * WXC;
        const __half* B = S + (cur * 2 + 1) * WXC;

#pragma unroll
        for (int ks = 0; ks < 2; ks++) {
            int ko = ks * 16;
            uint32_t bf[4][2];
#pragma unroll
            for (int nt = 0; nt < 4; nt++) {
                int r = wn * 32 + nt * 8 + g;
                bf[nt][0] = *(const uint32_t*)&B[r * WXS + ko + 2 * tq];
                bf[nt][1] = *(const uint32_t*)&B[r * WXS + ko + 2 * tq + 8];
            }
#pragma unroll
            for (int mt = 0; mt < 4; mt++) {
                int r0 = wm * 64 + mt * 16 + g, r1 = r0 + 8;
                uint32_t af[4];
                af[0] = *(const uint32_t*)&A[r0 * WXS + ko + 2 * tq];
                af[1] = *(const uint32_t*)&A[r1 * WXS + ko + 2 * tq];
                af[2] = *(const uint32_t*)&A[r0 * WXS + ko + 2 * tq + 8];
                af[3] = *(const uint32_t*)&A[r1 * WXS + ko + 2 * tq + 8];
#pragma unroll
                for (int nt = 0; nt < 4; nt++) mma16816h(acc[mt][nt], af, bf[nt]);
            }
        }
        __syncthreads();
    }

#pragma unroll
    for (int mt = 0; mt < 4; mt++) {
        size_t row = m0 + wm * 64 + mt * 16 + g;
#pragma unroll
        for (int nt = 0; nt < 4; nt++) {
            int col = n0 + wn * 32 + nt * 8 + 2 * tq;
            g_wx[row * GATES + col]           = acc[mt][nt][0] + bias[col];
            g_wx[row * GATES + col + 1]       = acc[mt][nt][1] + bias[col + 1];
            g_wx[(row + 8) * GATES + col]     = acc[mt][nt][2] + bias[col];
            g_wx[(row + 8) * GATES + col + 1] = acc[mt][nt][3] + bias[col + 1];
        }
    }
}

// ---------------- persistent LSTM recurrence v8: 512 threads, 4-way k-split ---
// 16 warps: grp = w>>2 owns k in [grp*256, +256); wm = w&3 owns batch rows
// [wm*16, +16). 4 warps/SMSP -> tensor pipe latency hiding. Each group's
// epilogue finalizes exactly one C-fragment j-slot (j == grp), so the 4-way
// partial reduction ships 3 slots per warp through a stride-17 smem exchange.
#define RSTR 1032                                  // fp16 elems per R row
#define HSTR 72
#define HBUF_B (16 * HSTR * 2)                     // 2304 B per (warp,buf)
#define H_REGION (32 * HBUF_B)                     // 16 warps x 2 bufs = 73728 B
#define RED_OFF (32 * RSTR * 2 + H_REGION)         // 66048 + 73728
#define RED_SZ (16 * 32 * 17 * 4)                  // 34816 B
#define SMEM_PERS (RED_OFF + RED_SZ)               // 174592 B

__device__ __forceinline__ void stage_warp(uint32_t hbase_sm,
                                           const __half* hsrc,
                                           int w, int grp, int wm,
                                           int kc, int b, int lane)
{
#pragma unroll
    for (int s = 0; s < 4; s++) {
        int id = s * 32 + lane;                    // 0..127
        int row = id >> 3, segk = id & 7;
        const __half* src = hsrc
            + (size_t)(wm * 16 + row) * HID + grp * 256 + kc * 64 + segk * 8;
        uint32_t dst = hbase_sm
            + (uint32_t)((w * 2 + b) * HBUF_B + row * (HSTR * 2) + segk * 16);
        asm volatile("cp.async.cg.shared.global [%0], [%1], 16;" :: "r"(dst), "l"(src));
    }
    asm volatile("cp.async.commit_group;");
}

__global__ __launch_bounds__(512) void lstm_persistent(float* __restrict__ out_base)
{
    extern __shared__ __align__(16) unsigned char smem_raw[];
    __half* Rf = (__half*)smem_raw;
    __half* Hbase = Rf + 32 * RSTR;
    float* Red = (float*)(smem_raw + RED_OFF);
    uint32_t hbase_sm = (uint32_t)__cvta_generic_to_shared(Hbase);

    const int tid  = threadIdx.x;
    const int lane = tid & 31, w = tid >> 5;
    const int g = lane >> 2, tq = lane & 3;
    const int grp = w >> 2, wm = w & 3;
    const int hc0 = blockIdx.x * 8;

    // load fp16 R slice into smem once: rows 0..31 = gate*8 + c8
    for (int rep = 0; rep < 8; rep++) {
        int id = rep * 512 + tid;
        int row = id >> 7, seg = id & 127;
        size_t src = (size_t)((row >> 3) * HID + hc0 + (row & 7)) * HID + seg * 8;
        *(uint4*)&Rf[row * RSTR + seg * 8] = *(const uint4*)&g_Rf[src];
    }
    __syncthreads();

    // this thread's single epilogue output (j == grp)
    const int jj = grp >> 1, cm = grp & 1;
    const int brow = wm * 16 + g + jj * 8;
    const int col  = hc0 + 2 * tq + cm;
    const int oidx = brow * HID + col;
    float c_reg = 0.f;

    for (int t = 0; t < T_STEPS; t++) {
        // prefetch this thread's wx values (DRAM, independent of h)
        float wxp[4];
        {
            const float* wb = g_wx + (size_t)t * BATCH * GATES + (size_t)brow * GATES;
#pragma unroll
            for (int gate = 0; gate < 4; gate++)
                wxp[gate] = ldcg_f(wb + gate * HID + col);
        }

        float acc[4][4];
#pragma unroll
        for (int nt = 0; nt < 4; nt++)
#pragma unroll
            for (int r = 0; r < 4; r++) acc[nt][r] = 0.f;

        if (t > 0) {
            const __half* hsrc = g_hf[(t - 1) & 1];

            stage_warp(hbase_sm, hsrc, w, grp, wm, 0, 0, lane);
            stage_warp(hbase_sm, hsrc, w, grp, wm, 1, 1, lane);

            for (int kc = 0; kc < 4; kc++) {
                int cur = kc & 1;
                if (kc < 3) asm volatile("cp.async.wait_group 1;");
                else        asm volatile("cp.async.wait_group 0;");

                const __half* HC = (const __half*)
                    ((const unsigned char*)Hbase + (w * 2 + cur) * HBUF_B);
#pragma unroll
                for (int kt = 0; kt < 4; kt++) {
                    int ko = kt * 16 + 2 * tq;
                    uint32_t ah[4];
                    ah[0] = *(const uint32_t*)&HC[g * HSTR + ko];
                    ah[1] = *(const uint32_t*)&HC[(g + 8) * HSTR + ko];
                    ah[2] = *(const uint32_t*)&HC[g * HSTR + ko + 8];
                    ah[3] = *(const uint32_t*)&HC[(g + 8) * HSTR + ko + 8];
                    int kR = grp * 256 + kc * 64 + kt * 16 + 2 * tq;
                    uint32_t bf[4][2];
#pragma unroll
                    for (int nt = 0; nt < 4; nt++) {
                        int rr = nt * 8 + g;
                        bf[nt][0] = *(const uint32_t*)&Rf[rr * RSTR + kR];
                        bf[nt][1] = *(const uint32_t*)&Rf[rr * RSTR + kR + 8];
                    }
#pragma unroll
                    for (int nt = 0; nt < 4; nt++) mma16816h(acc[nt], ah, bf[nt]);
                }
                if (kc + 2 < 4)
                    stage_warp(hbase_sm, hsrc, w, grp, wm, kc + 2, cur, lane);
            }
        }

        // 4-way cross-group reduction: every warp publishes all 16 partials
        {
            float* slot = Red + (size_t)(w * 32 + lane) * 17;
#pragma unroll
            for (int nt = 0; nt < 4; nt++)
#pragma unroll
                for (int j = 0; j < 4; j++) slot[nt * 4 + j] = acc[nt][j];
        }
        __syncthreads();

        {
            // sum own j-slot over the 3 other contributor groups
            float v[4];
#pragma unroll
            for (int nt = 0; nt < 4; nt++) v[nt] = acc[nt][grp];
#pragma unroll
            for (int c = 0; c < 4; c++) {
                if (c == grp) continue;
                const float* slot = Red + (size_t)(((c * 4 + wm) * 32 + lane)) * 17;
#pragma unroll
                for (int nt = 0; nt < 4; nt++) v[nt] += slot[nt * 4 + grp];
            }

            float vi = v[0] + wxp[0];
            float vg = v[1] + wxp[1];
            float vf = v[2] + wxp[2];
            float vo = v[3] + wxp[3];
            float ii = sigmoid_fast(vi);
            float gg = tanh_fast(vg);
            float ff = sigmoid_fast(vf);
            float oo = sigmoid_fast(vo);
            float cn = ff * c_reg + ii * gg;
            c_reg = cn;
            float h = oo * tanh_fast(cn);
            out_base[(size_t)t * BATCH * HID + oidx] = h;
            g_hf[t & 1][oidx] = __float2half_rn(h);
            if (t == T_STEPS - 1) {
                size_t base = (size_t)T_STEPS * BATCH * HID;
                out_base[base + oidx] = h;
                out_base[base + BATCH * HID + oidx] = cn;
            }
        }

        // device-wide barrier: per-CTA flag slots (proven)
        if (t < T_STEPS - 1) {
            __threadfence();
            __syncthreads();
            if (tid == 0)
                asm volatile("st.global.cg.u32 [%0], %1;"
                             :: "l"(&g_arrive[blockIdx.x * 8]), "r"(t + 1));
            unsigned target = t + 1;
            bool ok;
            do {
                unsigned v = target;
                if (tid < NCTA)
                    asm volatile("ld.global.cg.u32 %0, [%1];"
                                 : "=r"(v) : "l"(&g_arrive[tid * 8]));
                ok = (v >= target);
            } while (!__syncthreads_and(ok));
            __threadfence();
        }
    }

    // cleanup for graph replay (after ALL CTAs complete)
    if (tid == 0) {
        __threadfence();
        atomicAdd(&g_bar, 1u);
        if (blockIdx.x == 0) {
            while (atomicAdd(&g_bar, 0u) < NCTA) __nanosleep(100);
            for (int i = 0; i < NCTA; i++) g_arrive[i * 8] = 0;
            __threadfence();
            g_bar = 0;
        }
    }
}

extern "C" void kernel_launch(void* const* d_in, const int* in_sizes, int n_in,
                              void* d_out, int out_size)
{
    const float* x    = (const float*)d_in[0];
    const float* Wk   = (const float*)d_in[1];
    const float* Rk   = (const float*)d_in[2];
    const float* bias = (const float*)d_in[3];
    float* out = (float*)d_out;

    cudaFuncSetAttribute(lstm_persistent,
                         cudaFuncAttributeMaxDynamicSharedMemorySize, SMEM_PERS);
    cudaFuncSetAttribute(wx_mma,
                         cudaFuncAttributeMaxDynamicSharedMemorySize, WX_SMEM);

    size_t nx = (size_t)T_STEPS * BATCH * IN_DIM;
    convert_x<<<(unsigned)((nx + 255) / 256), 256>>>(x);
    convert_W<<<dim3(GATES / 32, IN_DIM / 32), dim3(32, 8)>>>(Wk);
    convert_R<<<dim3(GATES / 32, HID / 32), dim3(32, 8)>>>(Rk);

    wx_mma<<<dim3(GATES / 128, (T_STEPS * BATCH) / 128), 256, WX_SMEM>>>(bias);

    lstm_persistent<<<NCTA, 512, SMEM_PERS>>>(out);
}

// round 16
// speedup vs baseline: 3.4140x; 1.2685x over previous
#include <cuda_runtime.h>
#include <cuda_bf16.h>
#include <cuda_fp16.h>
#include <math.h>
#include <stdint.h>

#define T_STEPS 512
#define BATCH   64
#define IN_DIM  1024
#define HID     1024
#define GATES   4096   // 4*HID, gate order i,g,f,o
#define NCTA    128

// ---------------- device scratch ----------------
__device__ float g_wx[(size_t)T_STEPS * BATCH * GATES];   // 512 MB
__device__ unsigned g_ctr;                                // step barrier counter
__device__ unsigned g_bar;                                // end-of-launch cleanup

__device__ __half g_xf[(size_t)T_STEPS * BATCH * IN_DIM]; // fp16 x
__device__ __half g_Wf[(size_t)GATES * IN_DIM];           // fp16 W transposed [N][K]
__device__ __half g_Rf[(size_t)GATES * HID];              // fp16 R transposed [N][K]
__device__ __half g_hf[2][BATCH * HID];                   // fp16 ping-pong h

// ---------------- helpers ----------------
__device__ __forceinline__ void mma16816h(float* c, const uint32_t* a, const uint32_t* b)
{
    asm volatile(
        "mma.sync.aligned.m16n8k16.row.col.f32.f16.f16.f32 "
        "{%0,%1,%2,%3}, {%4,%5,%6,%7}, {%8,%9}, {%0,%1,%2,%3};"
        : "+f"(c[0]), "+f"(c[1]), "+f"(c[2]), "+f"(c[3])
        : "r"(a[0]), "r"(a[1]), "r"(a[2]), "r"(a[3]), "r"(b[0]), "r"(b[1]));
}

__device__ __forceinline__ float tanh_fast(float x)
{
    float y;
    asm("tanh.approx.f32 %0, %1;" : "=f"(y) : "f"(x));
    return y;
}
__device__ __forceinline__ float sigmoid_fast(float x)
{
    return 0.5f * tanh_fast(0.5f * x) + 0.5f;
}

__device__ __forceinline__ float ldcg_f(const float* p)
{
    float v;
    asm volatile("ld.global.cg.f32 %0, [%1];" : "=f"(v) : "l"(p));
    return v;
}

// ---------------- conversion kernels ----------------
__global__ void convert_x(const float* __restrict__ x)
{
    size_t i = (size_t)blockIdx.x * blockDim.x + threadIdx.x;
    if (i < (size_t)T_STEPS * BATCH * IN_DIM)
        g_xf[i] = __float2half_rn(x[i]);
}

__global__ void convert_W(const float* __restrict__ src)
{
    __shared__ float tile[32][33];
    int n0 = blockIdx.x * 32, k0 = blockIdx.y * 32;
    int tx = threadIdx.x, ty = threadIdx.y;
#pragma unroll
    for (int i = 0; i < 32; i += 8)
        tile[ty + i][tx] = src[(size_t)(k0 + ty + i) * GATES + n0 + tx];
    __syncthreads();
#pragma unroll
    for (int i = 0; i < 32; i += 8)
        g_Wf[(size_t)(n0 + ty + i) * IN_DIM + k0 + tx] = __float2half_rn(tile[tx][ty + i]);
}

__global__ void convert_R(const float* __restrict__ src)
{
    __shared__ float tile[32][33];
    int n0 = blockIdx.x * 32, k0 = blockIdx.y * 32;
    int tx = threadIdx.x, ty = threadIdx.y;
#pragma unroll
    for (int i = 0; i < 32; i += 8)
        tile[ty + i][tx] = src[(size_t)(k0 + ty + i) * GATES + n0 + tx];
    __syncthreads();
#pragma unroll
    for (int i = 0; i < 32; i += 8)
        g_Rf[(size_t)(n0 + ty + i) * HID + k0 + tx] = __float2half_rn(tile[tx][ty + i]);
}

// ---------------- wx GEMM: fp16 single-pass, cp.async double-buffered ---------
#define WXS 40
#define WXC (128 * WXS)
#define WX_SMEM (2 * 2 * WXC * 2)       // 40960 B

__device__ __forceinline__ void wx_stage(uint32_t smb, size_t m0, int n0,
                                         int k0, int b, int tid)
{
#pragma unroll
    for (int arr = 0; arr < 2; arr++) {
        const __half* sp = arr ? g_Wf : g_xf;
        size_t base = arr ? (size_t)n0 : m0;
#pragma unroll
        for (int rep = 0; rep < 2; rep++) {
            int id = tid + rep * 256;
            int row = id >> 2, seg = id & 3;
            const __half* src = sp + (base + row) * IN_DIM + k0 + seg * 8;
            uint32_t dst = smb + (uint32_t)(((b * 2 + arr) * WXC
                                             + row * WXS + seg * 8) * 2);
            asm volatile("cp.async.cg.shared.global [%0], [%1], 16;"
                         :: "r"(dst), "l"(src));
        }
    }
    asm volatile("cp.async.commit_group;");
}

__global__ __launch_bounds__(256) void wx_mma(const float* __restrict__ bias)
{
    extern __shared__ __align__(16) unsigned char wxsm[];
    __half* S = (__half*)wxsm;
    uint32_t smb = (uint32_t)__cvta_generic_to_shared(S);

    int tid  = threadIdx.x;
    int lane = tid & 31, w = tid >> 5;
    int g = lane >> 2, tq = lane & 3;
    size_t m0 = (size_t)blockIdx.y * 128;
    int n0 = blockIdx.x * 128;
    int wm = w & 1, wn = w >> 1;

    float acc[4][4][4];
#pragma unroll
    for (int mt = 0; mt < 4; mt++)
#pragma unroll
        for (int nt = 0; nt < 4; nt++)
#pragma unroll
            for (int r = 0; r < 4; r++) acc[mt][nt][r] = 0.f;

    wx_stage(smb, m0, n0, 0, 0, tid);

    for (int kc = 0; kc < 32; kc++) {
        int cur = kc & 1;
        if (kc < 31) {
            wx_stage(smb, m0, n0, (kc + 1) * 32, cur ^ 1, tid);
            asm volatile("cp.async.wait_group 1;");
        } else {
            asm volatile("cp.async.wait_group 0;");
        }
        __syncthreads();

        const __half* A = S + (cur * 2 + 0) * WXC;
        const __half* B = S + (cur * 2 + 1) * WXC;

#pragma unroll
        for (int ks = 0; ks < 2; ks++) {
            int ko = ks * 16;
            uint32_t bf[4][2];
#pragma unroll
            for (int nt = 0; nt < 4; nt++) {
                int r = wn * 32 + nt * 8 + g;
                bf[nt][0] = *(const uint32_t*)&B[r * WXS + ko + 2 * tq];
                bf[nt][1] = *(const uint32_t*)&B[r * WXS + ko + 2 * tq + 8];
            }
#pragma unroll
            for (int mt = 0; mt < 4; mt++) {
                int r0 = wm * 64 + mt * 16 + g, r1 = r0 + 8;
                uint32_t af[4];
                af[0] = *(const uint32_t*)&A[r0 * WXS + ko + 2 * tq];
                af[1] = *(const uint32_t*)&A[r1 * WXS + ko + 2 * tq];
                af[2] = *(const uint32_t*)&A[r0 * WXS + ko + 2 * tq + 8];
                af[3] = *(const uint32_t*)&A[r1 * WXS + ko + 2 * tq + 8];
#pragma unroll
                for (int nt = 0; nt < 4; nt++) mma16816h(acc[mt][nt], af, bf[nt]);
            }
        }
        __syncthreads();
    }

#pragma unroll
    for (int mt = 0; mt < 4; mt++) {
        size_t row = m0 + wm * 64 + mt * 16 + g;
#pragma unroll
        for (int nt = 0; nt < 4; nt++) {
            int col = n0 + wn * 32 + nt * 8 + 2 * tq;
            g_wx[row * GATES + col]           = acc[mt][nt][0] + bias[col];
            g_wx[row * GATES + col + 1]       = acc[mt][nt][1] + bias[col + 1];
            g_wx[(row + 8) * GATES + col]     = acc[mt][nt][2] + bias[col];
            g_wx[(row + 8) * GATES + col + 1] = acc[mt][nt][3] + bias[col + 1];
        }
    }
}

// ---------------- persistent LSTM recurrence v9 ----------------
// R15 structure (512 thr, 4-way k-split) with a minimal-critical-path barrier:
//   publish = syncthreads (CTA release) + ONE red.release.gpu.add by tid 0
//   detect  = tid 0 polls ld.acquire.gpu on the counter; others park at bar
// fp32 out_base store deferred past the barrier (g_hf is the only dependency).
#define RSTR 1032
#define HSTR 72
#define HBUF_B (16 * HSTR * 2)                     // 2304 B per (warp,buf)
#define H_REGION (32 * HBUF_B)                     // 73728 B
#define RED_OFF (32 * RSTR * 2 + H_REGION)
#define RED_SZ (16 * 32 * 17 * 4)                  // 34816 B
#define SMEM_PERS (RED_OFF + RED_SZ)               // 174592 B

__device__ __forceinline__ void stage_warp(uint32_t hbase_sm,
                                           const __half* hsrc,
                                           int w, int grp, int wm,
                                           int kc, int b, int lane)
{
#pragma unroll
    for (int s = 0; s < 4; s++) {
        int id = s * 32 + lane;
        int row = id >> 3, segk = id & 7;
        const __half* src = hsrc
            + (size_t)(wm * 16 + row) * HID + grp * 256 + kc * 64 + segk * 8;
        uint32_t dst = hbase_sm
            + (uint32_t)((w * 2 + b) * HBUF_B + row * (HSTR * 2) + segk * 16);
        asm volatile("cp.async.cg.shared.global [%0], [%1], 16;" :: "r"(dst), "l"(src));
    }
    asm volatile("cp.async.commit_group;");
}

__global__ __launch_bounds__(512) void lstm_persistent(float* __restrict__ out_base)
{
    extern __shared__ __align__(16) unsigned char smem_raw[];
    __half* Rf = (__half*)smem_raw;
    __half* Hbase = Rf + 32 * RSTR;
    float* Red = (float*)(smem_raw + RED_OFF);
    uint32_t hbase_sm = (uint32_t)__cvta_generic_to_shared(Hbase);

    const int tid  = threadIdx.x;
    const int lane = tid & 31, w = tid >> 5;
    const int g = lane >> 2, tq = lane & 3;
    const int grp = w >> 2, wm = w & 3;
    const int hc0 = blockIdx.x * 8;

    for (int rep = 0; rep < 8; rep++) {
        int id = rep * 512 + tid;
        int row = id >> 7, seg = id & 127;
        size_t src = (size_t)((row >> 3) * HID + hc0 + (row & 7)) * HID + seg * 8;
        *(uint4*)&Rf[row * RSTR + seg * 8] = *(const uint4*)&g_Rf[src];
    }
    __syncthreads();

    const int jj = grp >> 1, cm = grp & 1;
    const int brow = wm * 16 + g + jj * 8;
    const int col  = hc0 + 2 * tq + cm;
    const int oidx = brow * HID + col;
    float c_reg = 0.f;

    for (int t = 0; t < T_STEPS; t++) {
        float wxp[4];
        {
            const float* wb = g_wx + (size_t)t * BATCH * GATES + (size_t)brow * GATES;
#pragma unroll
            for (int gate = 0; gate < 4; gate++)
                wxp[gate] = ldcg_f(wb + gate * HID + col);
        }

        float acc[4][4];
#pragma unroll
        for (int nt = 0; nt < 4; nt++)
#pragma unroll
            for (int r = 0; r < 4; r++) acc[nt][r] = 0.f;

        if (t > 0) {
            const __half* hsrc = g_hf[(t - 1) & 1];

            stage_warp(hbase_sm, hsrc, w, grp, wm, 0, 0, lane);
            stage_warp(hbase_sm, hsrc, w, grp, wm, 1, 1, lane);

            for (int kc = 0; kc < 4; kc++) {
                int cur = kc & 1;
                if (kc < 3) asm volatile("cp.async.wait_group 1;");
                else        asm volatile("cp.async.wait_group 0;");

                const __half* HC = (const __half*)
                    ((const unsigned char*)Hbase + (w * 2 + cur) * HBUF_B);
#pragma unroll
                for (int kt = 0; kt < 4; kt++) {
                    int ko = kt * 16 + 2 * tq;
                    uint32_t ah[4];
                    ah[0] = *(const uint32_t*)&HC[g * HSTR + ko];
                    ah[1] = *(const uint32_t*)&HC[(g + 8) * HSTR + ko];
                    ah[2] = *(const uint32_t*)&HC[g * HSTR + ko + 8];
                    ah[3] = *(const uint32_t*)&HC[(g + 8) * HSTR + ko + 8];
                    int kR = grp * 256 + kc * 64 + kt * 16 + 2 * tq;
                    uint32_t bf[4][2];
#pragma unroll
                    for (int nt = 0; nt < 4; nt++) {
                        int rr = nt * 8 + g;
                        bf[nt][0] = *(const uint32_t*)&Rf[rr * RSTR + kR];
                        bf[nt][1] = *(const uint32_t*)&Rf[rr * RSTR + kR + 8];
                    }
#pragma unroll
                    for (int nt = 0; nt < 4; nt++) mma16816h(acc[nt], ah, bf[nt]);
                }
                if (kc + 2 < 4)
                    stage_warp(hbase_sm, hsrc, w, grp, wm, kc + 2, cur, lane);
            }
        }

        // 4-way cross-group reduction: publish only the 3 j-slots others need
        {
            float* slot = Red + (size_t)(w * 32 + lane) * 17;
#pragma unroll
            for (int nt = 0; nt < 4; nt++)
#pragma unroll
                for (int j = 0; j < 4; j++)
                    if (j != grp) slot[nt * 4 + j] = acc[nt][j];
        }
        __syncthreads();

        float h, cn;
        {
            float v[4];
#pragma unroll
            for (int nt = 0; nt < 4; nt++) v[nt] = acc[nt][grp];
#pragma unroll
            for (int c = 0; c < 4; c++) {
                if (c == grp) continue;
                const float* slot = Red + (size_t)(((c * 4 + wm) * 32 + lane)) * 17;
#pragma unroll
                for (int nt = 0; nt < 4; nt++) v[nt] += slot[nt * 4 + grp];
            }

            float ii = sigmoid_fast(v[0] + wxp[0]);
            float gg = tanh_fast(v[1] + wxp[1]);
            float ff = sigmoid_fast(v[2] + wxp[2]);
            float oo = sigmoid_fast(v[3] + wxp[3]);
            cn = ff * c_reg + ii * gg;
            c_reg = cn;
            h = oo * tanh_fast(cn);
            // the ONLY store the next step depends on:
            g_hf[t & 1][oidx] = __float2half_rn(h);
        }

        // publish + detect (grid release/acquire via one counter)
        if (t < T_STEPS - 1) {
            __syncthreads();                    // CTA-scope release of g_hf stores
            if (tid == 0) {
                asm volatile("red.release.gpu.global.add.u32 [%0], 1;"
                             :: "l"(&g_ctr) : "memory");
                unsigned target = (unsigned)NCTA * (unsigned)(t + 1);
                unsigned v;
                do {
                    asm volatile("ld.acquire.gpu.global.u32 %0, [%1];"
                                 : "=r"(v) : "l"(&g_ctr) : "memory");
                } while (v < target);
            }
            __syncthreads();                    // distribute acquire to all warps
        }

        // deferred fp32 output store — off the publish critical path
        out_base[(size_t)t * BATCH * HID + oidx] = h;
        if (t == T_STEPS - 1) {
            size_t base = (size_t)T_STEPS * BATCH * HID;
            out_base[base + oidx] = h;
            out_base[base + BATCH * HID + oidx] = cn;
        }
    }

    // cleanup for graph replay (after ALL CTAs complete)
    if (tid == 0) {
        __threadfence();
        atomicAdd(&g_bar, 1u);
        if (blockIdx.x == 0) {
            while (atomicAdd(&g_bar, 0u) < NCTA) __nanosleep(100);
            g_ctr = 0;
            __threadfence();
            g_bar = 0;
        }
    }
}

extern "C" void kernel_launch(void* const* d_in, const int* in_sizes, int n_in,
                              void* d_out, int out_size)
{
    const float* x    = (const float*)d_in[0];
    const float* Wk   = (const float*)d_in[1];
    const float* Rk   = (const float*)d_in[2];
    const float* bias = (const float*)d_in[3];
    float* out = (float*)d_out;

    cudaFuncSetAttribute(lstm_persistent,
                         cudaFuncAttributeMaxDynamicSharedMemorySize, SMEM_PERS);
    cudaFuncSetAttribute(wx_mma,
                         cudaFuncAttributeMaxDynamicSharedMemorySize, WX_SMEM);

    size_t nx = (size_t)T_STEPS * BATCH * IN_DIM;
    convert_x<<<(unsigned)((nx + 255) / 256), 256>>>(x);
    convert_W<<<dim3(GATES / 32, IN_DIM / 32), dim3(32, 8)>>>(Wk);
    convert_R<<<dim3(GATES / 32, HID / 32), dim3(32, 8)>>>(Rk);

    wx_mma<<<dim3(GATES / 128, (T_STEPS * BATCH) / 128), 256, WX_SMEM>>>(bias);

    lstm_persistent<<<NCTA, 512, SMEM_PERS>>>(out);
}